// round 2
// baseline (speedup 1.0000x reference)
#include <cuda_runtime.h>
#include <cstdint>

#define N_NODES 50000
#define N_EDGES 800000

// ---------------- scratch (static device globals; no allocs allowed) --------
__device__ float g_bufA[(size_t)N_NODES * 256];   // aggregation output
__device__ float g_bufB[(size_t)N_NODES * 256];   // MLP hidden
__device__ float g_bufC[(size_t)N_NODES * 256];   // layer output (next layer input)
__device__ int   g_row[N_NODES + 1];              // CSR row offsets (by dst)
__device__ int   g_cnt[N_NODES];                  // degree counts / fill cursors
__device__ int   g_srcs[N_EDGES];                 // src node per CSR slot

// ---------------- CSR build -------------------------------------------------
__global__ void k_zero_cnt() {
    int i = blockIdx.x * blockDim.x + threadIdx.x;
    if (i < N_NODES) g_cnt[i] = 0;
}

__global__ void k_count(const int* __restrict__ ei) {
    int e = blockIdx.x * blockDim.x + threadIdx.x;
    if (e < N_EDGES) {
        int dst = ei[N_EDGES + e];
        if (dst >= 0 && dst < N_NODES) atomicAdd(&g_cnt[dst], 1);
    }
}

// single-block exclusive scan over 50000 counts; also resets counts to 0
__global__ void k_scan() {
    __shared__ int ssum[1024];
    const int t = threadIdx.x;
    const int CH = (N_NODES + 1023) / 1024;   // 49
    const int base = t * CH;
    int s = 0;
    for (int i = 0; i < CH; i++) {
        int idx = base + i;
        if (idx < N_NODES) s += g_cnt[idx];
    }
    ssum[t] = s;
    __syncthreads();
    // Hillis-Steele inclusive scan
    for (int off = 1; off < 1024; off <<= 1) {
        int v = (t >= off) ? ssum[t - off] : 0;
        __syncthreads();
        ssum[t] += v;
        __syncthreads();
    }
    int run = ssum[t] - s;   // exclusive prefix for this chunk
    for (int i = 0; i < CH; i++) {
        int idx = base + i;
        if (idx < N_NODES) {
            int c = g_cnt[idx];
            g_row[idx] = run;
            run += c;
            g_cnt[idx] = 0;   // reset as fill cursor
        }
    }
    if (t == 1023) g_row[N_NODES] = ssum[1023];
}

__global__ void k_fill(const int* __restrict__ ei) {
    int e = blockIdx.x * blockDim.x + threadIdx.x;
    if (e < N_EDGES) {
        int src = ei[e];
        int dst = ei[N_EDGES + e];
        if (src >= 0 && src < N_NODES && dst >= 0 && dst < N_NODES) {
            int pos = atomicAdd(&g_cnt[dst], 1);
            g_srcs[g_row[dst] + pos] = src;
        }
    }
}

// ---------------- aggregation: agg[i] = x[i] + sum_{e:dst=i} x[src[e]] ------
// warp per node; VEC float4 per lane (VEC=1 -> F=128, VEC=2 -> F=256)
template <int VEC>
__global__ void k_agg(const float* __restrict__ x, float* __restrict__ out) {
    const int node = (blockIdx.x * blockDim.x + threadIdx.x) >> 5;
    if (node >= N_NODES) return;
    const int lane = threadIdx.x & 31;
    const int F = VEC * 128;

    float4 acc[VEC];
    const float4* xr = (const float4*)(x + (size_t)node * F);
#pragma unroll
    for (int v = 0; v < VEC; v++) acc[v] = xr[lane + 32 * v];

    const int s = g_row[node];
    const int e = g_row[node + 1];
    for (int i = s; i < e; i++) {
        const int src = g_srcs[i];
        const float4* xs = (const float4*)(x + (size_t)src * F);
#pragma unroll
        for (int v = 0; v < VEC; v++) {
            float4 t = __ldg(&xs[lane + 32 * v]);
            acc[v].x += t.x; acc[v].y += t.y; acc[v].z += t.z; acc[v].w += t.w;
        }
    }
    float4* orow = (float4*)(out + (size_t)node * F);
#pragma unroll
    for (int v = 0; v < VEC; v++) orow[lane + 32 * v] = acc[v];
}

// ---------------- fused SGEMM + bias (+ReLU): C[M,N] = act(A[M,K]@W[K,N]+b) -
// BM=64, BN=64, BK=16, 256 threads, 4x4 micro-tile per thread.
template <bool RELU>
__launch_bounds__(256)
__global__ void k_sgemm(const float* __restrict__ A, const float* __restrict__ W,
                        const float* __restrict__ bias, float* __restrict__ C,
                        int M, int K, int N) {
    __shared__ float As[16][64];   // [k][m]
    __shared__ float Ws[16][64];   // [k][n]

    const int tid  = threadIdx.x;
    const int tidM = tid >> 4;      // 0..15
    const int tidN = tid & 15;      // 0..15
    const int row0 = blockIdx.y * 64;
    const int col0 = blockIdx.x * 64;

    // A-tile load mapping: 64 rows x 16 cols -> one float4 per thread
    const int ar  = tid >> 2;       // 0..63 (row within tile)
    const int ac4 = tid & 3;        // 0..3  (float4 within K-slab)
    // W-tile load mapping: 16 rows x 64 cols -> one float4 per thread
    const int wr  = tid >> 4;       // 0..15
    const int wc4 = tid & 15;       // 0..15

    float acc[4][4];
#pragma unroll
    for (int i = 0; i < 4; i++)
#pragma unroll
        for (int j = 0; j < 4; j++) acc[i][j] = 0.f;

    for (int kb = 0; kb < K; kb += 16) {
        float4 av = make_float4(0.f, 0.f, 0.f, 0.f);
        const int gr = row0 + ar;
        if (gr < M) av = *(const float4*)(A + (size_t)gr * K + kb + ac4 * 4);
        As[ac4 * 4 + 0][ar] = av.x;
        As[ac4 * 4 + 1][ar] = av.y;
        As[ac4 * 4 + 2][ar] = av.z;
        As[ac4 * 4 + 3][ar] = av.w;

        float4 wv = *(const float4*)(W + (size_t)(kb + wr) * N + col0 + wc4 * 4);
        *(float4*)&Ws[wr][wc4 * 4] = wv;
        __syncthreads();

#pragma unroll
        for (int k = 0; k < 16; k++) {
            float a[4], w[4];
            *(float4*)a = *(const float4*)&As[k][tidM * 4];
            *(float4*)w = *(const float4*)&Ws[k][tidN * 4];
#pragma unroll
            for (int i = 0; i < 4; i++)
#pragma unroll
                for (int j = 0; j < 4; j++) acc[i][j] += a[i] * w[j];
        }
        __syncthreads();
    }

    float b[4];
    *(float4*)b = *(const float4*)(bias + col0 + tidN * 4);
#pragma unroll
    for (int i = 0; i < 4; i++) {
        const int gr = row0 + tidM * 4 + i;
        if (gr < M) {
            float4 o;
            o.x = acc[i][0] + b[0];
            o.y = acc[i][1] + b[1];
            o.z = acc[i][2] + b[2];
            o.w = acc[i][3] + b[3];
            if (RELU) {
                o.x = fmaxf(o.x, 0.f); o.y = fmaxf(o.y, 0.f);
                o.z = fmaxf(o.z, 0.f); o.w = fmaxf(o.w, 0.f);
            }
            *(float4*)(C + (size_t)gr * N + col0 + tidN * 4) = o;
        }
    }
}

// ---------------- launch ----------------------------------------------------
static inline void launch_gemm(const float* A, const float* W, const float* b,
                               float* C, int M, int K, int N, bool relu) {
    dim3 grid(N / 64, (M + 63) / 64);
    if (relu) k_sgemm<true><<<grid, 256>>>(A, W, b, C, M, K, N);
    else      k_sgemm<false><<<grid, 256>>>(A, W, b, C, M, K, N);
}

extern "C" void kernel_launch(void* const* d_in, const int* in_sizes, int n_in,
                              void* d_out, int out_size) {
    const float* x  = (const float*)d_in[0];
    const int*   ei = (const int*)d_in[1];   // int32! (JAX x64 disabled downgrades int64)
    const float *w1a = (const float*)d_in[2],  *b1a = (const float*)d_in[3];
    const float *w1b = (const float*)d_in[4],  *b1b = (const float*)d_in[5];
    const float *w2a = (const float*)d_in[6],  *b2a = (const float*)d_in[7];
    const float *w2b = (const float*)d_in[8],  *b2b = (const float*)d_in[9];
    const float *w3a = (const float*)d_in[10], *b3a = (const float*)d_in[11];
    const float *w3b = (const float*)d_in[12], *b3b = (const float*)d_in[13];
    float* out = (float*)d_out;

    float *bufA, *bufB, *bufC;
    cudaGetSymbolAddress((void**)&bufA, g_bufA);
    cudaGetSymbolAddress((void**)&bufB, g_bufB);
    cudaGetSymbolAddress((void**)&bufC, g_bufC);

    // --- CSR build (per launch; deterministic up to fp-sum order) ---
    k_zero_cnt<<<(N_NODES + 255) / 256, 256>>>();
    k_count<<<(N_EDGES + 255) / 256, 256>>>(ei);
    k_scan<<<1, 1024>>>();
    k_fill<<<(N_EDGES + 255) / 256, 256>>>(ei);

    const int AGG_BLOCKS = (N_NODES * 32 + 255) / 256;

    // --- layer 1: F=128 -> hid 128 -> out 256, outer ReLU fused ---
    k_agg<1><<<AGG_BLOCKS, 256>>>(x, bufA);
    launch_gemm(bufA, w1a, b1a, bufB, N_NODES, 128, 128, true);
    launch_gemm(bufB, w1b, b1b, bufC, N_NODES, 128, 256, true);

    // --- layer 2: F=256 -> hid 256 -> out 128, outer ReLU fused ---
    k_agg<2><<<AGG_BLOCKS, 256>>>(bufC, bufA);
    launch_gemm(bufA, w2a, b2a, bufB, N_NODES, 256, 256, true);
    launch_gemm(bufB, w2b, b2b, bufC, N_NODES, 256, 128, true);

    // --- layer 3: F=128 -> hid 128 -> out 128 (no final ReLU) ---
    k_agg<1><<<AGG_BLOCKS, 256>>>(bufC, bufA);
    launch_gemm(bufA, w3a, b3a, bufB, N_NODES, 128, 128, true);
    launch_gemm(bufB, w3b, b3b, out, N_NODES, 128, 128, false);
}

// round 4
// speedup vs baseline: 1.4080x; 1.4080x over previous
#include <cuda_runtime.h>
#include <cuda_bf16.h>
#include <cstdint>

#define MN 50000
#define NE 800000

// ---------------- scratch (device globals; no allocs allowed) ---------------
__device__ __nv_bfloat16 g_aggH[(size_t)MN * 256];
__device__ __nv_bfloat16 g_aggL[(size_t)MN * 256];
__device__ __nv_bfloat16 g_hH[(size_t)MN * 256];
__device__ __nv_bfloat16 g_hL[(size_t)MN * 256];
__device__ float         g_f32[(size_t)MN * 256];
__device__ __nv_bfloat16 g_wH[6][65536];
__device__ __nv_bfloat16 g_wL[6][65536];
__device__ int g_row[MN + 1];
__device__ int g_cnt[MN];
__device__ int g_srcs[NE];

// ---------------- CSR build -------------------------------------------------
__global__ void k_zero_cnt() {
    int i = blockIdx.x * blockDim.x + threadIdx.x;
    if (i < MN) g_cnt[i] = 0;
}
__global__ void k_count(const int* __restrict__ ei) {
    int e = blockIdx.x * blockDim.x + threadIdx.x;
    if (e < NE) {
        int dst = ei[NE + e];
        if (dst >= 0 && dst < MN) atomicAdd(&g_cnt[dst], 1);
    }
}
__global__ void k_scan() {
    __shared__ int ssum[1024];
    const int t = threadIdx.x;
    const int CH = (MN + 1023) / 1024;
    const int base = t * CH;
    int s = 0;
    for (int i = 0; i < CH; i++) { int idx = base + i; if (idx < MN) s += g_cnt[idx]; }
    ssum[t] = s;
    __syncthreads();
    for (int off = 1; off < 1024; off <<= 1) {
        int v = (t >= off) ? ssum[t - off] : 0;
        __syncthreads();
        ssum[t] += v;
        __syncthreads();
    }
    int run = ssum[t] - s;
    for (int i = 0; i < CH; i++) {
        int idx = base + i;
        if (idx < MN) { int c = g_cnt[idx]; g_row[idx] = run; run += c; g_cnt[idx] = 0; }
    }
    if (t == 1023) g_row[MN] = ssum[1023];
}
__global__ void k_fill(const int* __restrict__ ei) {
    int e = blockIdx.x * blockDim.x + threadIdx.x;
    if (e < NE) {
        int src = ei[e];
        int dst = ei[NE + e];
        if (src >= 0 && src < MN && dst >= 0 && dst < MN) {
            int pos = atomicAdd(&g_cnt[dst], 1);
            g_srcs[g_row[dst] + pos] = src;
        }
    }
}

// ---------------- weight convert: W[K,N] fp32 -> Bhi/Blo[N,K] bf16 ----------
__global__ void k_wcvt(const float* __restrict__ W, __nv_bfloat16* __restrict__ hi,
                       __nv_bfloat16* __restrict__ lo, int K, int N) {
    int i = blockIdx.x * blockDim.x + threadIdx.x;
    if (i < K * N) {
        int k = i / N, n = i % N;
        float v = W[i];
        __nv_bfloat16 h = __float2bfloat16(v);
        hi[(size_t)n * K + k] = h;
        lo[(size_t)n * K + k] = __float2bfloat16(v - __bfloat162float(h));
    }
}

// ---------------- aggregation: fp32 in -> bf16 hi/lo out --------------------
__device__ __forceinline__ uint32_t pack_bf16(float a, float b, float* ra, float* rb) {
    __nv_bfloat16 ha = __float2bfloat16(a), hb = __float2bfloat16(b);
    *ra = a - __bfloat162float(ha);
    *rb = b - __bfloat162float(hb);
    return ((uint32_t)__bfloat16_as_ushort(hb) << 16) | (uint32_t)__bfloat16_as_ushort(ha);
}

template <int VEC>
__global__ void k_agg(const float* __restrict__ x, __nv_bfloat16* __restrict__ oh,
                      __nv_bfloat16* __restrict__ ol) {
    const int node = (blockIdx.x * blockDim.x + threadIdx.x) >> 5;
    if (node >= MN) return;
    const int lane = threadIdx.x & 31;
    const int F = VEC * 128;

    float4 acc[VEC];
    const float4* xr = (const float4*)(x + (size_t)node * F);
#pragma unroll
    for (int v = 0; v < VEC; v++) acc[v] = xr[lane + 32 * v];

    const int s = g_row[node];
    const int e = g_row[node + 1];
    for (int i = s; i < e; i++) {
        const int src = g_srcs[i];
        const float4* xs = (const float4*)(x + (size_t)src * F);
#pragma unroll
        for (int v = 0; v < VEC; v++) {
            float4 t = __ldg(&xs[lane + 32 * v]);
            acc[v].x += t.x; acc[v].y += t.y; acc[v].z += t.z; acc[v].w += t.w;
        }
    }
#pragma unroll
    for (int v = 0; v < VEC; v++) {
        float r0, r1, r2, r3;
        uint32_t h01 = pack_bf16(acc[v].x, acc[v].y, &r0, &r1);
        uint32_t h23 = pack_bf16(acc[v].z, acc[v].w, &r2, &r3);
        __nv_bfloat16 l0 = __float2bfloat16(r0), l1 = __float2bfloat16(r1);
        __nv_bfloat16 l2 = __float2bfloat16(r2), l3 = __float2bfloat16(r3);
        uint32_t q01 = ((uint32_t)__bfloat16_as_ushort(l1) << 16) | (uint32_t)__bfloat16_as_ushort(l0);
        uint32_t q23 = ((uint32_t)__bfloat16_as_ushort(l3) << 16) | (uint32_t)__bfloat16_as_ushort(l2);
        size_t off = (size_t)node * F + lane * 4 + 128 * v;
        *(uint2*)(oh + off) = make_uint2(h01, h23);
        *(uint2*)(ol + off) = make_uint2(q01, q23);
    }
}

// ---------------- mma.sync bf16 GEMM (3-pass hi/lo split) --------------------
// C[M,N] = act(A[M,K] @ W[K,N] + bias)
// A as Ahi/Alo [M,K] bf16; B as Bhi/Blo [N,K] bf16 (pre-transposed).
// EPI: 0 = fp32+ReLU, 1 = fp32, 2 = bf16 hi/lo + ReLU
#define PITCH 40   // bf16 elements per smem row (conflict-free: 20 banks stride)

__device__ __forceinline__ void mma16816(float* d, const uint32_t* a, const uint32_t* b) {
    asm volatile("mma.sync.aligned.m16n8k16.row.col.f32.bf16.bf16.f32 "
                 "{%0,%1,%2,%3}, {%4,%5,%6,%7}, {%8,%9}, {%0,%1,%2,%3};"
                 : "+f"(d[0]), "+f"(d[1]), "+f"(d[2]), "+f"(d[3])
                 : "r"(a[0]), "r"(a[1]), "r"(a[2]), "r"(a[3]), "r"(b[0]), "r"(b[1]));
}

template <int EPI>
__launch_bounds__(256)
__global__ void k_mmagemm(const __nv_bfloat16* __restrict__ Ahi, const __nv_bfloat16* __restrict__ Alo,
                          const __nv_bfloat16* __restrict__ Bhi, const __nv_bfloat16* __restrict__ Blo,
                          const float* __restrict__ bias,
                          float* __restrict__ outF, __nv_bfloat16* __restrict__ outH,
                          __nv_bfloat16* __restrict__ outL, int M, int K, int N) {
    __shared__ __nv_bfloat16 sAh[128 * PITCH], sAl[128 * PITCH];
    __shared__ __nv_bfloat16 sBh[128 * PITCH], sBl[128 * PITCH];
    __shared__ float sbias[128];

    const int tid = threadIdx.x, warp = tid >> 5, lane = tid & 31;
    const int g = lane >> 2, tig = lane & 3;
    const int wm = warp >> 1, wn = warp & 1;      // warp grid 4 x 2, warp tile 32x64
    const int m0 = blockIdx.x * 128, n0 = blockIdx.y * 128;

    if (tid < 128) sbias[tid] = bias[n0 + tid];

    float acc[2][8][4];
#pragma unroll
    for (int i = 0; i < 2; i++)
#pragma unroll
        for (int j = 0; j < 8; j++)
#pragma unroll
            for (int r = 0; r < 4; r++) acc[i][j][r] = 0.f;

    const int NKT = K >> 5;
    for (int kt = 0; kt < NKT; kt++) {
        const int kb = kt * 32;
        if (kt > 0) __syncthreads();
        // load A/B hi+lo tiles: 128 rows x 32 bf16 each; 2 uint4 per thread per tile
#pragma unroll
        for (int i = 0; i < 2; i++) {
            const int idx = tid + 256 * i;
            const int r = idx >> 2, c4 = idx & 3;
            const int so = r * PITCH + c4 * 8;
            const int gr = m0 + r;
            uint4 vh = make_uint4(0u, 0u, 0u, 0u), vl = vh;
            if (gr < M) {
                vh = *(const uint4*)(Ahi + (size_t)gr * K + kb + c4 * 8);
                vl = *(const uint4*)(Alo + (size_t)gr * K + kb + c4 * 8);
            }
            *(uint4*)&sAh[so] = vh;
            *(uint4*)&sAl[so] = vl;
            uint4 wh = *(const uint4*)(Bhi + (size_t)(n0 + r) * K + kb + c4 * 8);
            uint4 wl = *(const uint4*)(Blo + (size_t)(n0 + r) * K + kb + c4 * 8);
            *(uint4*)&sBh[so] = wh;
            *(uint4*)&sBl[so] = wl;
        }
        __syncthreads();

#pragma unroll
        for (int pass = 0; pass < 3; pass++) {
            const __nv_bfloat16* As = (pass < 2) ? sAh : sAl;
            const __nv_bfloat16* Bs = (pass == 1) ? sBl : sBh;
#pragma unroll
            for (int k16 = 0; k16 < 2; k16++) {
                const int c0 = k16 * 16 + tig * 2;
                uint32_t a[2][4];
#pragma unroll
                for (int i = 0; i < 2; i++) {
                    const int r0 = wm * 32 + i * 16 + g;
                    a[i][0] = *(const uint32_t*)&As[r0 * PITCH + c0];
                    a[i][1] = *(const uint32_t*)&As[(r0 + 8) * PITCH + c0];
                    a[i][2] = *(const uint32_t*)&As[r0 * PITCH + c0 + 8];
                    a[i][3] = *(const uint32_t*)&As[(r0 + 8) * PITCH + c0 + 8];
                }
                uint32_t b[8][2];
#pragma unroll
                for (int j = 0; j < 8; j++) {
                    const int n = wn * 64 + j * 8 + g;
                    b[j][0] = *(const uint32_t*)&Bs[n * PITCH + c0];
                    b[j][1] = *(const uint32_t*)&Bs[n * PITCH + c0 + 8];
                }
#pragma unroll
                for (int i = 0; i < 2; i++)
#pragma unroll
                    for (int j = 0; j < 8; j++) mma16816(acc[i][j], a[i], b[j]);
            }
        }
    }
    __syncthreads();

    // epilogue
#pragma unroll
    for (int i = 0; i < 2; i++) {
        const int r0 = m0 + wm * 32 + i * 16 + g;
#pragma unroll
        for (int half = 0; half < 2; half++) {
            const int row = r0 + half * 8;
            if (row >= M) continue;
#pragma unroll
            for (int j = 0; j < 8; j++) {
                const int cl = wn * 64 + j * 8 + tig * 2;    // local col (0..127)
                float v0 = acc[i][j][2 * half + 0] + sbias[cl];
                float v1 = acc[i][j][2 * half + 1] + sbias[cl + 1];
                if (EPI != 1) { v0 = fmaxf(v0, 0.f); v1 = fmaxf(v1, 0.f); }
                const size_t o = (size_t)row * N + n0 + cl;
                if (EPI == 2) {
                    float r0f, r1f;
                    uint32_t hp = pack_bf16(v0, v1, &r0f, &r1f);
                    __nv_bfloat16 l0 = __float2bfloat16(r0f), l1 = __float2bfloat16(r1f);
                    uint32_t lp = ((uint32_t)__bfloat16_as_ushort(l1) << 16) |
                                  (uint32_t)__bfloat16_as_ushort(l0);
                    *(uint32_t*)(outH + o) = hp;
                    *(uint32_t*)(outL + o) = lp;
                } else {
                    *(float2*)(outF + o) = make_float2(v0, v1);
                }
            }
        }
    }
}

// ---------------- launch ----------------------------------------------------
static inline void launch_gemm(int epi, const __nv_bfloat16* Ahi, const __nv_bfloat16* Alo,
                               const __nv_bfloat16* Bhi, const __nv_bfloat16* Blo,
                               const float* bias, float* outF, __nv_bfloat16* outH,
                               __nv_bfloat16* outL, int M, int K, int N) {
    dim3 grid((M + 127) / 128, N / 128);
    if (epi == 0)      k_mmagemm<0><<<grid, 256>>>(Ahi, Alo, Bhi, Blo, bias, outF, outH, outL, M, K, N);
    else if (epi == 1) k_mmagemm<1><<<grid, 256>>>(Ahi, Alo, Bhi, Blo, bias, outF, outH, outL, M, K, N);
    else               k_mmagemm<2><<<grid, 256>>>(Ahi, Alo, Bhi, Blo, bias, outF, outH, outL, M, K, N);
}

extern "C" void kernel_launch(void* const* d_in, const int* in_sizes, int n_in,
                              void* d_out, int out_size) {
    const float* x  = (const float*)d_in[0];
    const int*   ei = (const int*)d_in[1];   // int32 (JAX x64 disabled)
    const float* W[6]  = {(const float*)d_in[2], (const float*)d_in[4], (const float*)d_in[6],
                          (const float*)d_in[8], (const float*)d_in[10], (const float*)d_in[12]};
    const float* Bv[6] = {(const float*)d_in[3], (const float*)d_in[5], (const float*)d_in[7],
                          (const float*)d_in[9], (const float*)d_in[11], (const float*)d_in[13]};
    const int WK[6] = {128, 128, 256, 256, 128, 128};
    const int WN[6] = {128, 256, 256, 128, 128, 128};
    float* out = (float*)d_out;

    __nv_bfloat16 *aggH, *aggL, *hH, *hL, *wH, *wL;
    float* f32;
    cudaGetSymbolAddress((void**)&aggH, g_aggH);
    cudaGetSymbolAddress((void**)&aggL, g_aggL);
    cudaGetSymbolAddress((void**)&hH, g_hH);
    cudaGetSymbolAddress((void**)&hL, g_hL);
    cudaGetSymbolAddress((void**)&wH, g_wH);
    cudaGetSymbolAddress((void**)&wL, g_wL);
    cudaGetSymbolAddress((void**)&f32, g_f32);

    // --- CSR build ---
    k_zero_cnt<<<(MN + 255) / 256, 256>>>();
    k_count<<<(NE + 255) / 256, 256>>>(ei);
    k_scan<<<1, 1024>>>();
    k_fill<<<(NE + 255) / 256, 256>>>(ei);

    // --- weight conversion (transpose + bf16 split) ---
    for (int i = 0; i < 6; i++) {
        int n = WK[i] * WN[i];
        k_wcvt<<<(n + 255) / 256, 256>>>(W[i], wH + (size_t)i * 65536, wL + (size_t)i * 65536,
                                         WK[i], WN[i]);
    }

    const int AGG_BLOCKS = (MN * 32 + 255) / 256;

    // --- layer 1 ---
    k_agg<1><<<AGG_BLOCKS, 256>>>(x, aggH, aggL);
    launch_gemm(2, aggH, aggL, wH + 0 * 65536, wL + 0 * 65536, Bv[0], nullptr, hH, hL, MN, 128, 128);
    launch_gemm(0, hH, hL,     wH + 1 * 65536, wL + 1 * 65536, Bv[1], f32, nullptr, nullptr, MN, 128, 256);

    // --- layer 2 ---
    k_agg<2><<<AGG_BLOCKS, 256>>>(f32, aggH, aggL);
    launch_gemm(2, aggH, aggL, wH + 2 * 65536, wL + 2 * 65536, Bv[2], nullptr, hH, hL, MN, 256, 256);
    launch_gemm(0, hH, hL,     wH + 3 * 65536, wL + 3 * 65536, Bv[3], f32, nullptr, nullptr, MN, 256, 128);

    // --- layer 3 ---
    k_agg<1><<<AGG_BLOCKS, 256>>>(f32, aggH, aggL);
    launch_gemm(2, aggH, aggL, wH + 4 * 65536, wL + 4 * 65536, Bv[4], nullptr, hH, hL, MN, 128, 128);
    launch_gemm(1, hH, hL,     wH + 5 * 65536, wL + 5 * 65536, Bv[5], out, nullptr, nullptr, MN, 128, 128);
}

// round 5
// speedup vs baseline: 1.6397x; 1.1646x over previous
#include <cuda_runtime.h>
#include <cuda_bf16.h>
#include <cstdint>

#define MN  50000
#define MNP 50176          // padded to 392*128 (unconditional GEMM tile loads)
#define NE  800000

// ---------------- scratch (device globals; no allocs allowed) ---------------
__device__ __nv_bfloat16 g_aggH[(size_t)MNP * 256];
__device__ __nv_bfloat16 g_aggL[(size_t)MNP * 256];
__device__ __nv_bfloat16 g_hH[(size_t)MNP * 256];
__device__ __nv_bfloat16 g_hL[(size_t)MNP * 256];
__device__ float         g_f32[(size_t)MNP * 256];
__device__ __nv_bfloat16 g_wH[6][65536];
__device__ __nv_bfloat16 g_wL[6][65536];
__device__ int g_row[MN + 1];
__device__ int g_cnt[MN];
__device__ int g_srcs[NE];

// ---------------- helpers ---------------------------------------------------
__device__ __forceinline__ uint32_t smem_u32(const void* p) {
    return (uint32_t)__cvta_generic_to_shared((void*)p);
}
__device__ __forceinline__ void cp_async16(uint32_t dst, const void* src) {
    asm volatile("cp.async.cg.shared.global [%0], [%1], 16;" :: "r"(dst), "l"(src));
}
__device__ __forceinline__ void cp_commit() {
    asm volatile("cp.async.commit_group;" ::: "memory");
}
template <int n>
__device__ __forceinline__ void cp_wait() {
    asm volatile("cp.async.wait_group %0;" :: "n"(n) : "memory");
}

// ---------------- CSR build -------------------------------------------------
__global__ void k_zero_cnt() {
    int i = blockIdx.x * blockDim.x + threadIdx.x;
    if (i < MN) g_cnt[i] = 0;
}
__global__ void k_count(const int* __restrict__ ei) {
    int e = blockIdx.x * blockDim.x + threadIdx.x;
    if (e < NE) {
        int dst = ei[NE + e];
        if (dst >= 0 && dst < MN) atomicAdd(&g_cnt[dst], 1);
    }
}
__global__ void k_scan() {
    __shared__ int ssum[1024];
    const int t = threadIdx.x;
    const int CH = (MN + 1023) / 1024;
    const int base = t * CH;
    int s = 0;
    for (int i = 0; i < CH; i++) { int idx = base + i; if (idx < MN) s += g_cnt[idx]; }
    ssum[t] = s;
    __syncthreads();
    for (int off = 1; off < 1024; off <<= 1) {
        int v = (t >= off) ? ssum[t - off] : 0;
        __syncthreads();
        ssum[t] += v;
        __syncthreads();
    }
    int run = ssum[t] - s;
    for (int i = 0; i < CH; i++) {
        int idx = base + i;
        if (idx < MN) { int c = g_cnt[idx]; g_row[idx] = run; run += c; g_cnt[idx] = 0; }
    }
    if (t == 1023) g_row[MN] = ssum[1023];
}
__global__ void k_fill(const int* __restrict__ ei) {
    int e = blockIdx.x * blockDim.x + threadIdx.x;
    if (e < NE) {
        int src = ei[e];
        int dst = ei[NE + e];
        if (src >= 0 && src < MN && dst >= 0 && dst < MN) {
            int pos = atomicAdd(&g_cnt[dst], 1);
            g_srcs[g_row[dst] + pos] = src;
        }
    }
}

// ---------------- weight convert: W[K,N] fp32 -> Bhi/Blo[N,K] (tiled) -------
__global__ void k_wcvt(const float* __restrict__ W, __nv_bfloat16* __restrict__ hi,
                       __nv_bfloat16* __restrict__ lo, int K, int N) {
    __shared__ float t[32][33];
    const int kb = blockIdx.y * 32, nb = blockIdx.x * 32;
    const int tx = threadIdx.x, ty0 = threadIdx.y;
#pragma unroll
    for (int i = 0; i < 4; i++) {
        int ty = ty0 + 8 * i;
        t[ty][tx] = W[(size_t)(kb + ty) * N + nb + tx];
    }
    __syncthreads();
#pragma unroll
    for (int i = 0; i < 4; i++) {
        int n = ty0 + 8 * i;
        float v = t[tx][n];
        __nv_bfloat16 h = __float2bfloat16(v);
        hi[(size_t)(nb + n) * K + kb + tx] = h;
        lo[(size_t)(nb + n) * K + kb + tx] = __float2bfloat16(v - __bfloat162float(h));
    }
}

// ---------------- aggregation: fp32 in -> bf16 hi/lo out --------------------
__device__ __forceinline__ uint32_t pack_bf16(float a, float b, float* ra, float* rb) {
    __nv_bfloat16 ha = __float2bfloat16(a), hb = __float2bfloat16(b);
    *ra = a - __bfloat162float(ha);
    *rb = b - __bfloat162float(hb);
    return ((uint32_t)__bfloat16_as_ushort(hb) << 16) | (uint32_t)__bfloat16_as_ushort(ha);
}

template <int VEC>
__global__ void k_agg(const float* __restrict__ x, __nv_bfloat16* __restrict__ oh,
                      __nv_bfloat16* __restrict__ ol) {
    const int node = (blockIdx.x * blockDim.x + threadIdx.x) >> 5;
    if (node >= MN) return;
    const int lane = threadIdx.x & 31;
    const int F = VEC * 128;

    float4 acc[VEC];
    const float4* xr = (const float4*)(x + (size_t)node * F);
#pragma unroll
    for (int v = 0; v < VEC; v++) acc[v] = xr[lane + 32 * v];

    const int s = g_row[node];
    const int e = g_row[node + 1];
    for (int i = s; i < e; i++) {
        const int src = g_srcs[i];
        const float4* xs = (const float4*)(x + (size_t)src * F);
#pragma unroll
        for (int v = 0; v < VEC; v++) {
            float4 t = __ldg(&xs[lane + 32 * v]);
            acc[v].x += t.x; acc[v].y += t.y; acc[v].z += t.z; acc[v].w += t.w;
        }
    }
#pragma unroll
    for (int v = 0; v < VEC; v++) {
        float r0, r1, r2, r3;
        uint32_t h01 = pack_bf16(acc[v].x, acc[v].y, &r0, &r1);
        uint32_t h23 = pack_bf16(acc[v].z, acc[v].w, &r2, &r3);
        __nv_bfloat16 l0 = __float2bfloat16(r0), l1 = __float2bfloat16(r1);
        __nv_bfloat16 l2 = __float2bfloat16(r2), l3 = __float2bfloat16(r3);
        uint32_t q01 = ((uint32_t)__bfloat16_as_ushort(l1) << 16) | (uint32_t)__bfloat16_as_ushort(l0);
        uint32_t q23 = ((uint32_t)__bfloat16_as_ushort(l3) << 16) | (uint32_t)__bfloat16_as_ushort(l2);
        size_t off = (size_t)node * F + lane * 4 + 128 * v;
        *(uint2*)(oh + off) = make_uint2(h01, h23);
        *(uint2*)(ol + off) = make_uint2(q01, q23);
    }
}

// ---------------- mma.sync bf16 GEMM, cp.async double-buffered ---------------
// C[M,N] = act(A[M,K] @ W[K,N] + bias); 3-pass bf16 hi/lo split.
// EPI: 0 = fp32+ReLU, 1 = fp32, 2 = bf16 hi/lo + ReLU
#define PITCH 40                   // bf16 elems per smem row (80B, conflict-free)
#define TILE_B 10240               // one 128x32 bf16 array, 80B rows
#define BUF_B  (4 * TILE_B)        // Ah, Al, Bh, Bl
#define SM_TOTAL (2 * BUF_B + 512)

__device__ __forceinline__ void mma16816(float* d, const uint32_t* a, const uint32_t* b) {
    asm volatile("mma.sync.aligned.m16n8k16.row.col.f32.bf16.bf16.f32 "
                 "{%0,%1,%2,%3}, {%4,%5,%6,%7}, {%8,%9}, {%0,%1,%2,%3};"
                 : "+f"(d[0]), "+f"(d[1]), "+f"(d[2]), "+f"(d[3])
                 : "r"(a[0]), "r"(a[1]), "r"(a[2]), "r"(a[3]), "r"(b[0]), "r"(b[1]));
}

__device__ __forceinline__ void load_tile(
    char* smbase, const __nv_bfloat16* __restrict__ Ahi, const __nv_bfloat16* __restrict__ Alo,
    const __nv_bfloat16* __restrict__ Bhi, const __nv_bfloat16* __restrict__ Blo,
    int tid, int m0, int n0, int K, int kb) {
    const uint32_t s0 = smem_u32(smbase);
#pragma unroll
    for (int i = 0; i < 2; i++) {
        const int idx = tid + 256 * i;
        const int r = idx >> 2, c4 = idx & 3;
        const uint32_t so = (uint32_t)(r * 80 + c4 * 16);
        const size_t aoff = (size_t)(m0 + r) * K + kb + c4 * 8;
        const size_t boff = (size_t)(n0 + r) * K + kb + c4 * 8;
        cp_async16(s0 + so,              Ahi + aoff);
        cp_async16(s0 + TILE_B + so,     Alo + aoff);
        cp_async16(s0 + 2 * TILE_B + so, Bhi + boff);
        cp_async16(s0 + 3 * TILE_B + so, Blo + boff);
    }
}

template <int EPI>
__global__ __launch_bounds__(256, 2)
void k_mmagemm(const __nv_bfloat16* __restrict__ Ahi, const __nv_bfloat16* __restrict__ Alo,
               const __nv_bfloat16* __restrict__ Bhi, const __nv_bfloat16* __restrict__ Blo,
               const float* __restrict__ bias,
               float* __restrict__ outF, __nv_bfloat16* __restrict__ outH,
               __nv_bfloat16* __restrict__ outL, int M, int K, int N) {
    extern __shared__ char sm[];
    float* sbias = (float*)(sm + 2 * BUF_B);

    const int tid = threadIdx.x, warp = tid >> 5, lane = tid & 31;
    const int g = lane >> 2, tig = lane & 3;
    const int wm = warp >> 1, wn = warp & 1;      // 4x2 warp grid, 32x64 warp tile
    const int m0 = blockIdx.x * 128, n0 = blockIdx.y * 128;

    if (tid < 128) sbias[tid] = bias[n0 + tid];

    float acc[2][8][4];
#pragma unroll
    for (int i = 0; i < 2; i++)
#pragma unroll
        for (int j = 0; j < 8; j++)
#pragma unroll
            for (int r = 0; r < 4; r++) acc[i][j][r] = 0.f;

    const int NKT = K >> 5;
    load_tile(sm, Ahi, Alo, Bhi, Blo, tid, m0, n0, K, 0);
    cp_commit();

    for (int kt = 0; kt < NKT; kt++) {
        const int b = kt & 1;
        if (kt + 1 < NKT) {
            __syncthreads();   // all warps done reading buf b^1 (iter kt-1)
            load_tile(sm + (b ^ 1) * BUF_B, Ahi, Alo, Bhi, Blo, tid, m0, n0, K, (kt + 1) * 32);
            cp_commit();
            cp_wait<1>();
        } else {
            cp_wait<0>();
        }
        __syncthreads();

        const __nv_bfloat16* sAh = (const __nv_bfloat16*)(sm + b * BUF_B);
        const __nv_bfloat16* sAl = (const __nv_bfloat16*)(sm + b * BUF_B + TILE_B);
        const __nv_bfloat16* sBh = (const __nv_bfloat16*)(sm + b * BUF_B + 2 * TILE_B);
        const __nv_bfloat16* sBl = (const __nv_bfloat16*)(sm + b * BUF_B + 3 * TILE_B);

#pragma unroll
        for (int pass = 0; pass < 3; pass++) {
            const __nv_bfloat16* As = (pass < 2) ? sAh : sAl;
            const __nv_bfloat16* Bs = (pass == 1) ? sBl : sBh;
#pragma unroll
            for (int k16 = 0; k16 < 2; k16++) {
                const int c0 = k16 * 16 + tig * 2;
                uint32_t a[2][4];
#pragma unroll
                for (int i = 0; i < 2; i++) {
                    const int r0 = wm * 32 + i * 16 + g;
                    a[i][0] = *(const uint32_t*)&As[r0 * PITCH + c0];
                    a[i][1] = *(const uint32_t*)&As[(r0 + 8) * PITCH + c0];
                    a[i][2] = *(const uint32_t*)&As[r0 * PITCH + c0 + 8];
                    a[i][3] = *(const uint32_t*)&As[(r0 + 8) * PITCH + c0 + 8];
                }
                uint32_t b2[8][2];
#pragma unroll
                for (int j = 0; j < 8; j++) {
                    const int n = wn * 64 + j * 8 + g;
                    b2[j][0] = *(const uint32_t*)&Bs[n * PITCH + c0];
                    b2[j][1] = *(const uint32_t*)&Bs[n * PITCH + c0 + 8];
                }
#pragma unroll
                for (int i = 0; i < 2; i++)
#pragma unroll
                    for (int j = 0; j < 8; j++) mma16816(acc[i][j], a[i], b2[j]);
            }
        }
    }

    // epilogue (registers + sbias only; no extra sync needed)
#pragma unroll
    for (int i = 0; i < 2; i++) {
        const int r0 = m0 + wm * 32 + i * 16 + g;
#pragma unroll
        for (int half = 0; half < 2; half++) {
            const int row = r0 + half * 8;
            if (row >= M) continue;
#pragma unroll
            for (int j = 0; j < 8; j++) {
                const int cl = wn * 64 + j * 8 + tig * 2;
                float v0 = acc[i][j][2 * half + 0] + sbias[cl];
                float v1 = acc[i][j][2 * half + 1] + sbias[cl + 1];
                if (EPI != 1) { v0 = fmaxf(v0, 0.f); v1 = fmaxf(v1, 0.f); }
                const size_t o = (size_t)row * N + n0 + cl;
                if (EPI == 2) {
                    float r0f, r1f;
                    uint32_t hp = pack_bf16(v0, v1, &r0f, &r1f);
                    __nv_bfloat16 l0 = __float2bfloat16(r0f), l1 = __float2bfloat16(r1f);
                    uint32_t lp = ((uint32_t)__bfloat16_as_ushort(l1) << 16) |
                                  (uint32_t)__bfloat16_as_ushort(l0);
                    *(uint32_t*)(outH + o) = hp;
                    *(uint32_t*)(outL + o) = lp;
                } else {
                    *(float2*)(outF + o) = make_float2(v0, v1);
                }
            }
        }
    }
}

// ---------------- launch ----------------------------------------------------
static inline void launch_gemm(int epi, const __nv_bfloat16* Ahi, const __nv_bfloat16* Alo,
                               const __nv_bfloat16* Bhi, const __nv_bfloat16* Blo,
                               const float* bias, float* outF, __nv_bfloat16* outH,
                               __nv_bfloat16* outL, int M, int K, int N) {
    dim3 grid((M + 127) / 128, N / 128);
    if (epi == 0)      k_mmagemm<0><<<grid, 256, SM_TOTAL>>>(Ahi, Alo, Bhi, Blo, bias, outF, outH, outL, M, K, N);
    else if (epi == 1) k_mmagemm<1><<<grid, 256, SM_TOTAL>>>(Ahi, Alo, Bhi, Blo, bias, outF, outH, outL, M, K, N);
    else               k_mmagemm<2><<<grid, 256, SM_TOTAL>>>(Ahi, Alo, Bhi, Blo, bias, outF, outH, outL, M, K, N);
}

extern "C" void kernel_launch(void* const* d_in, const int* in_sizes, int n_in,
                              void* d_out, int out_size) {
    const float* x  = (const float*)d_in[0];
    const int*   ei = (const int*)d_in[1];   // int32 (JAX x64 disabled)
    const float* W[6]  = {(const float*)d_in[2], (const float*)d_in[4], (const float*)d_in[6],
                          (const float*)d_in[8], (const float*)d_in[10], (const float*)d_in[12]};
    const float* Bv[6] = {(const float*)d_in[3], (const float*)d_in[5], (const float*)d_in[7],
                          (const float*)d_in[9], (const float*)d_in[11], (const float*)d_in[13]};
    const int WK[6] = {128, 128, 256, 256, 128, 128};
    const int WN[6] = {128, 256, 256, 128, 128, 128};
    float* out = (float*)d_out;

    __nv_bfloat16 *aggH, *aggL, *hH, *hL, *wH, *wL;
    float* f32;
    cudaGetSymbolAddress((void**)&aggH, g_aggH);
    cudaGetSymbolAddress((void**)&aggL, g_aggL);
    cudaGetSymbolAddress((void**)&hH, g_hH);
    cudaGetSymbolAddress((void**)&hL, g_hL);
    cudaGetSymbolAddress((void**)&wH, g_wH);
    cudaGetSymbolAddress((void**)&wL, g_wL);
    cudaGetSymbolAddress((void**)&f32, g_f32);

    cudaFuncSetAttribute(k_mmagemm<0>, cudaFuncAttributeMaxDynamicSharedMemorySize, SM_TOTAL);
    cudaFuncSetAttribute(k_mmagemm<1>, cudaFuncAttributeMaxDynamicSharedMemorySize, SM_TOTAL);
    cudaFuncSetAttribute(k_mmagemm<2>, cudaFuncAttributeMaxDynamicSharedMemorySize, SM_TOTAL);

    // --- CSR build ---
    k_zero_cnt<<<(MN + 255) / 256, 256>>>();
    k_count<<<(NE + 255) / 256, 256>>>(ei);
    k_scan<<<1, 1024>>>();
    k_fill<<<(NE + 255) / 256, 256>>>(ei);

    // --- weight conversion (tiled transpose + bf16 split) ---
    for (int i = 0; i < 6; i++) {
        dim3 g(WN[i] / 32, WK[i] / 32), blk(32, 8);
        k_wcvt<<<g, blk>>>(W[i], wH + (size_t)i * 65536, wL + (size_t)i * 65536, WK[i], WN[i]);
    }

    const int AGG_BLOCKS = (MN * 32 + 255) / 256;

    // --- layer 1 ---
    k_agg<1><<<AGG_BLOCKS, 256>>>(x, aggH, aggL);
    launch_gemm(2, aggH, aggL, wH + 0 * 65536, wL + 0 * 65536, Bv[0], nullptr, hH, hL, MN, 128, 128);
    launch_gemm(0, hH, hL,     wH + 1 * 65536, wL + 1 * 65536, Bv[1], f32, nullptr, nullptr, MN, 128, 256);

    // --- layer 2 ---
    k_agg<2><<<AGG_BLOCKS, 256>>>(f32, aggH, aggL);
    launch_gemm(2, aggH, aggL, wH + 2 * 65536, wL + 2 * 65536, Bv[2], nullptr, hH, hL, MN, 256, 256);
    launch_gemm(0, hH, hL,     wH + 3 * 65536, wL + 3 * 65536, Bv[3], f32, nullptr, nullptr, MN, 256, 128);

    // --- layer 3 ---
    k_agg<1><<<AGG_BLOCKS, 256>>>(f32, aggH, aggL);
    launch_gemm(2, aggH, aggL, wH + 4 * 65536, wL + 4 * 65536, Bv[4], nullptr, hH, hL, MN, 128, 128);
    launch_gemm(1, hH, hL,     wH + 5 * 65536, wL + 5 * 65536, Bv[5], out, nullptr, nullptr, MN, 128, 128);
}

// round 6
// speedup vs baseline: 1.6551x; 1.0094x over previous
#include <cuda_runtime.h>
#include <cuda_bf16.h>
#include <cstdint>

#define MN  50000
#define MNP 50176          // padded to 392*128 (unconditional GEMM tile loads)
#define NE  800000

// ---------------- scratch (device globals; no allocs allowed) ---------------
__device__ __nv_bfloat16 g_aggH[(size_t)MNP * 256];
__device__ __nv_bfloat16 g_aggL[(size_t)MNP * 256];
__device__ __nv_bfloat16 g_hH[(size_t)MNP * 256];
__device__ __nv_bfloat16 g_hL[(size_t)MNP * 256];
__device__ float         g_f32[(size_t)MNP * 256];
__device__ __nv_bfloat16 g_wH[6][65536];
__device__ __nv_bfloat16 g_wL[6][65536];
__device__ int g_row[MN + 1];
__device__ int g_cnt[MN];
__device__ int g_srcs[NE];

// ---------------- helpers ---------------------------------------------------
__device__ __forceinline__ uint32_t smem_u32(const void* p) {
    return (uint32_t)__cvta_generic_to_shared((void*)p);
}
__device__ __forceinline__ void cp_async16(uint32_t dst, const void* src) {
    asm volatile("cp.async.cg.shared.global [%0], [%1], 16;" :: "r"(dst), "l"(src));
}
__device__ __forceinline__ void cp_commit() {
    asm volatile("cp.async.commit_group;" ::: "memory");
}
template <int n>
__device__ __forceinline__ void cp_wait() {
    asm volatile("cp.async.wait_group %0;" :: "n"(n) : "memory");
}
__device__ __forceinline__ void ldsm_x4(uint32_t& r0, uint32_t& r1, uint32_t& r2,
                                        uint32_t& r3, uint32_t addr) {
    asm volatile("ldmatrix.sync.aligned.m8n8.x4.shared.b16 {%0,%1,%2,%3}, [%4];"
                 : "=r"(r0), "=r"(r1), "=r"(r2), "=r"(r3) : "r"(addr));
}

// ---------------- CSR build -------------------------------------------------
__global__ void k_zero_cnt() {
    int i = blockIdx.x * blockDim.x + threadIdx.x;
    if (i < MN) g_cnt[i] = 0;
}
__global__ void k_count(const int* __restrict__ ei) {
    int e = blockIdx.x * blockDim.x + threadIdx.x;
    if (e < NE) {
        int dst = ei[NE + e];
        if (dst >= 0 && dst < MN) atomicAdd(&g_cnt[dst], 1);
    }
}
__global__ void k_scan() {
    __shared__ int ssum[1024];
    const int t = threadIdx.x;
    const int CH = (MN + 1023) / 1024;
    const int base = t * CH;
    int s = 0;
    for (int i = 0; i < CH; i++) { int idx = base + i; if (idx < MN) s += g_cnt[idx]; }
    ssum[t] = s;
    __syncthreads();
    for (int off = 1; off < 1024; off <<= 1) {
        int v = (t >= off) ? ssum[t - off] : 0;
        __syncthreads();
        ssum[t] += v;
        __syncthreads();
    }
    int run = ssum[t] - s;
    for (int i = 0; i < CH; i++) {
        int idx = base + i;
        if (idx < MN) { int c = g_cnt[idx]; g_row[idx] = run; run += c; g_cnt[idx] = 0; }
    }
    if (t == 1023) g_row[MN] = ssum[1023];
}
__global__ void k_fill(const int* __restrict__ ei) {
    int e = blockIdx.x * blockDim.x + threadIdx.x;
    if (e < NE) {
        int src = ei[e];
        int dst = ei[NE + e];
        if (src >= 0 && src < MN && dst >= 0 && dst < MN) {
            int pos = atomicAdd(&g_cnt[dst], 1);
            g_srcs[g_row[dst] + pos] = src;
        }
    }
}

// ---------------- weight convert: W[K,N] fp32 -> Bhi/Blo[N,K] (tiled) -------
__global__ void k_wcvt(const float* __restrict__ W, __nv_bfloat16* __restrict__ hi,
                       __nv_bfloat16* __restrict__ lo, int K, int N) {
    __shared__ float t[32][33];
    const int kb = blockIdx.y * 32, nb = blockIdx.x * 32;
    const int tx = threadIdx.x, ty0 = threadIdx.y;
#pragma unroll
    for (int i = 0; i < 4; i++) {
        int ty = ty0 + 8 * i;
        t[ty][tx] = W[(size_t)(kb + ty) * N + nb + tx];
    }
    __syncthreads();
#pragma unroll
    for (int i = 0; i < 4; i++) {
        int n = ty0 + 8 * i;
        float v = t[tx][n];
        __nv_bfloat16 h = __float2bfloat16(v);
        hi[(size_t)(nb + n) * K + kb + tx] = h;
        lo[(size_t)(nb + n) * K + kb + tx] = __float2bfloat16(v - __bfloat162float(h));
    }
}

// ---------------- aggregation: fp32 in -> bf16 hi/lo out --------------------
__device__ __forceinline__ uint32_t pack_bf16(float a, float b, float* ra, float* rb) {
    __nv_bfloat16 ha = __float2bfloat16(a), hb = __float2bfloat16(b);
    *ra = a - __bfloat162float(ha);
    *rb = b - __bfloat162float(hb);
    return ((uint32_t)__bfloat16_as_ushort(hb) << 16) | (uint32_t)__bfloat16_as_ushort(ha);
}

template <int VEC>
__global__ void k_agg(const float* __restrict__ x, __nv_bfloat16* __restrict__ oh,
                      __nv_bfloat16* __restrict__ ol) {
    const int node = (blockIdx.x * blockDim.x + threadIdx.x) >> 5;
    if (node >= MN) return;
    const int lane = threadIdx.x & 31;
    const int F = VEC * 128;

    float4 acc[VEC];
    const float4* xr = (const float4*)(x + (size_t)node * F);
#pragma unroll
    for (int v = 0; v < VEC; v++) acc[v] = xr[lane + 32 * v];

    const int s = g_row[node];
    const int e = g_row[node + 1];
    for (int i = s; i < e; i += 32) {
        const int my = (i + lane < e) ? g_srcs[i + lane] : 0;
        const int cnt = min(32, e - i);
        for (int t = 0; t < cnt; t++) {
            const int src = __shfl_sync(0xffffffff, my, t);
            const float4* xs = (const float4*)(x + (size_t)src * F);
#pragma unroll
            for (int v = 0; v < VEC; v++) {
                float4 q = __ldg(&xs[lane + 32 * v]);
                acc[v].x += q.x; acc[v].y += q.y; acc[v].z += q.z; acc[v].w += q.w;
            }
        }
    }
#pragma unroll
    for (int v = 0; v < VEC; v++) {
        float r0, r1, r2, r3;
        uint32_t h01 = pack_bf16(acc[v].x, acc[v].y, &r0, &r1);
        uint32_t h23 = pack_bf16(acc[v].z, acc[v].w, &r2, &r3);
        __nv_bfloat16 l0 = __float2bfloat16(r0), l1 = __float2bfloat16(r1);
        __nv_bfloat16 l2 = __float2bfloat16(r2), l3 = __float2bfloat16(r3);
        uint32_t q01 = ((uint32_t)__bfloat16_as_ushort(l1) << 16) | (uint32_t)__bfloat16_as_ushort(l0);
        uint32_t q23 = ((uint32_t)__bfloat16_as_ushort(l3) << 16) | (uint32_t)__bfloat16_as_ushort(l2);
        size_t off = (size_t)node * F + lane * 4 + 128 * v;
        *(uint2*)(oh + off) = make_uint2(h01, h23);
        *(uint2*)(ol + off) = make_uint2(q01, q23);
    }
}

// ---------------- mma.sync bf16 GEMM, cp.async + ldmatrix --------------------
// C[M,N] = act(A[M,K] @ W[K,N] + bias); 3-pass bf16 hi/lo split.
// EPI: 0 = fp32+ReLU, 1 = fp32, 2 = bf16 hi/lo + ReLU
#define PITCH 40                   // bf16 elems per smem row (80B, conflict-free)
#define TILE_B 10240               // one 128x32 bf16 array, 80B rows
#define BUF_B  (4 * TILE_B)        // Ah, Al, Bh, Bl
#define SM_TOTAL (2 * BUF_B + 512)

__device__ __forceinline__ void mma16816(float* d, const uint32_t* a, const uint32_t* b) {
    asm volatile("mma.sync.aligned.m16n8k16.row.col.f32.bf16.bf16.f32 "
                 "{%0,%1,%2,%3}, {%4,%5,%6,%7}, {%8,%9}, {%0,%1,%2,%3};"
                 : "+f"(d[0]), "+f"(d[1]), "+f"(d[2]), "+f"(d[3])
                 : "r"(a[0]), "r"(a[1]), "r"(a[2]), "r"(a[3]), "r"(b[0]), "r"(b[1]));
}

__device__ __forceinline__ void load_tile(
    char* smbase, const __nv_bfloat16* __restrict__ Ahi, const __nv_bfloat16* __restrict__ Alo,
    const __nv_bfloat16* __restrict__ Bhi, const __nv_bfloat16* __restrict__ Blo,
    int tid, int m0, int n0, int K, int kb) {
    const uint32_t s0 = smem_u32(smbase);
#pragma unroll
    for (int i = 0; i < 2; i++) {
        const int idx = tid + 256 * i;
        const int r = idx >> 2, c4 = idx & 3;
        const uint32_t so = (uint32_t)(r * 80 + c4 * 16);
        const size_t aoff = (size_t)(m0 + r) * K + kb + c4 * 8;
        const size_t boff = (size_t)(n0 + r) * K + kb + c4 * 8;
        cp_async16(s0 + so,              Ahi + aoff);
        cp_async16(s0 + TILE_B + so,     Alo + aoff);
        cp_async16(s0 + 2 * TILE_B + so, Bhi + boff);
        cp_async16(s0 + 3 * TILE_B + so, Blo + boff);
    }
}

template <int EPI>
__global__ __launch_bounds__(256, 2)
void k_mmagemm(const __nv_bfloat16* __restrict__ Ahi, const __nv_bfloat16* __restrict__ Alo,
               const __nv_bfloat16* __restrict__ Bhi, const __nv_bfloat16* __restrict__ Blo,
               const float* __restrict__ bias,
               float* __restrict__ outF, __nv_bfloat16* __restrict__ outH,
               __nv_bfloat16* __restrict__ outL, int M, int K, int N) {
    extern __shared__ char sm[];
    float* sbias = (float*)(sm + 2 * BUF_B);

    const int tid = threadIdx.x, warp = tid >> 5, lane = tid & 31;
    const int g = lane >> 2, tig = lane & 3;
    const int wm = warp >> 1, wn = warp & 1;      // 4x2 warp grid, 32x64 warp tile
    const int m0 = blockIdx.x * 128, n0 = blockIdx.y * 128;

    if (tid < 128) sbias[tid] = bias[n0 + tid];

    // ldmatrix per-lane address offsets (in bf16 elements, relative to array base):
    // A tiles (16x16): lanes 0-15 rows base+(lane&15) col 0; lanes 16-31 same rows col +8
    const int aRow = wm * 32 + (lane & 15);
    const int aCol = (lane & 16) ? 8 : 0;
    const uint32_t aOffB = (uint32_t)(aRow * PITCH + aCol) * 2;  // +i*16 rows, +k16*16 cols
    // B tiles (16 n x 16 k per LDSM): lanes0-7 n+l k0 | 8-15 n+l k+8 | 16-23 n+8+l k0 | 24-31 n+8+l k+8
    const int bRow = wn * 64 + (lane & 7) + ((lane & 16) ? 8 : 0);
    const int bCol = (lane & 8) ? 8 : 0;
    const uint32_t bOffB = (uint32_t)(bRow * PITCH + bCol) * 2;  // +jj*16 rows, +k16*16 cols

    float acc[2][8][4];
#pragma unroll
    for (int i = 0; i < 2; i++)
#pragma unroll
        for (int j = 0; j < 8; j++)
#pragma unroll
            for (int r = 0; r < 4; r++) acc[i][j][r] = 0.f;

    const int NKT = K >> 5;
    load_tile(sm, Ahi, Alo, Bhi, Blo, tid, m0, n0, K, 0);
    cp_commit();
    const uint32_t smu = smem_u32(sm);

    for (int kt = 0; kt < NKT; kt++) {
        const int b = kt & 1;
        if (kt + 1 < NKT) {
            __syncthreads();
            load_tile(sm + (b ^ 1) * BUF_B, Ahi, Alo, Bhi, Blo, tid, m0, n0, K, (kt + 1) * 32);
            cp_commit();
            cp_wait<1>();
        } else {
            cp_wait<0>();
        }
        __syncthreads();

        const uint32_t sAhU = smu + b * BUF_B;
        const uint32_t sAlU = sAhU + TILE_B;
        const uint32_t sBhU = sAhU + 2 * TILE_B;
        const uint32_t sBlU = sAhU + 3 * TILE_B;

#pragma unroll
        for (int pass = 0; pass < 3; pass++) {
            const uint32_t aBase = ((pass < 2) ? sAhU : sAlU) + aOffB;
            const uint32_t bBase = ((pass == 1) ? sBlU : sBhU) + bOffB;
#pragma unroll
            for (int k16 = 0; k16 < 2; k16++) {
                const uint32_t kByte = (uint32_t)(k16 * 16 * 2);
                uint32_t a[2][4];
#pragma unroll
                for (int i = 0; i < 2; i++)
                    ldsm_x4(a[i][0], a[i][1], a[i][2], a[i][3],
                            aBase + kByte + (uint32_t)(i * 16 * PITCH * 2));
                uint32_t b2[8][2];
#pragma unroll
                for (int jj = 0; jj < 4; jj++)
                    ldsm_x4(b2[2 * jj][0], b2[2 * jj][1], b2[2 * jj + 1][0], b2[2 * jj + 1][1],
                            bBase + kByte + (uint32_t)(jj * 16 * PITCH * 2));
#pragma unroll
                for (int i = 0; i < 2; i++)
#pragma unroll
                    for (int j = 0; j < 8; j++) mma16816(acc[i][j], a[i], b2[j]);
            }
        }
    }

    // epilogue (registers + sbias only)
#pragma unroll
    for (int i = 0; i < 2; i++) {
        const int r0 = m0 + wm * 32 + i * 16 + g;
#pragma unroll
        for (int half = 0; half < 2; half++) {
            const int row = r0 + half * 8;
            if (row >= M) continue;
#pragma unroll
            for (int j = 0; j < 8; j++) {
                const int cl = wn * 64 + j * 8 + tig * 2;
                float v0 = acc[i][j][2 * half + 0] + sbias[cl];
                float v1 = acc[i][j][2 * half + 1] + sbias[cl + 1];
                if (EPI != 1) { v0 = fmaxf(v0, 0.f); v1 = fmaxf(v1, 0.f); }
                const size_t o = (size_t)row * N + n0 + cl;
                if (EPI == 2) {
                    float r0f, r1f;
                    uint32_t hp = pack_bf16(v0, v1, &r0f, &r1f);
                    __nv_bfloat16 l0 = __float2bfloat16(r0f), l1 = __float2bfloat16(r1f);
                    uint32_t lp = ((uint32_t)__bfloat16_as_ushort(l1) << 16) |
                                  (uint32_t)__bfloat16_as_ushort(l0);
                    *(uint32_t*)(outH + o) = hp;
                    *(uint32_t*)(outL + o) = lp;
                } else {
                    *(float2*)(outF + o) = make_float2(v0, v1);
                }
            }
        }
    }
}

// ---------------- launch ----------------------------------------------------
static inline void launch_gemm(int epi, const __nv_bfloat16* Ahi, const __nv_bfloat16* Alo,
                               const __nv_bfloat16* Bhi, const __nv_bfloat16* Blo,
                               const float* bias, float* outF, __nv_bfloat16* outH,
                               __nv_bfloat16* outL, int M, int K, int N) {
    dim3 grid((M + 127) / 128, N / 128);
    if (epi == 0)      k_mmagemm<0><<<grid, 256, SM_TOTAL>>>(Ahi, Alo, Bhi, Blo, bias, outF, outH, outL, M, K, N);
    else if (epi == 1) k_mmagemm<1><<<grid, 256, SM_TOTAL>>>(Ahi, Alo, Bhi, Blo, bias, outF, outH, outL, M, K, N);
    else               k_mmagemm<2><<<grid, 256, SM_TOTAL>>>(Ahi, Alo, Bhi, Blo, bias, outF, outH, outL, M, K, N);
}

extern "C" void kernel_launch(void* const* d_in, const int* in_sizes, int n_in,
                              void* d_out, int out_size) {
    const float* x  = (const float*)d_in[0];
    const int*   ei = (const int*)d_in[1];   // int32 (JAX x64 disabled)
    const float* W[6]  = {(const float*)d_in[2], (const float*)d_in[4], (const float*)d_in[6],
                          (const float*)d_in[8], (const float*)d_in[10], (const float*)d_in[12]};
    const float* Bv[6] = {(const float*)d_in[3], (const float*)d_in[5], (const float*)d_in[7],
                          (const float*)d_in[9], (const float*)d_in[11], (const float*)d_in[13]};
    const int WK[6] = {128, 128, 256, 256, 128, 128};
    const int WN[6] = {128, 256, 256, 128, 128, 128};
    float* out = (float*)d_out;

    __nv_bfloat16 *aggH, *aggL, *hH, *hL, *wH, *wL;
    float* f32;
    cudaGetSymbolAddress((void**)&aggH, g_aggH);
    cudaGetSymbolAddress((void**)&aggL, g_aggL);
    cudaGetSymbolAddress((void**)&hH, g_hH);
    cudaGetSymbolAddress((void**)&hL, g_hL);
    cudaGetSymbolAddress((void**)&wH, g_wH);
    cudaGetSymbolAddress((void**)&wL, g_wL);
    cudaGetSymbolAddress((void**)&f32, g_f32);

    cudaFuncSetAttribute(k_mmagemm<0>, cudaFuncAttributeMaxDynamicSharedMemorySize, SM_TOTAL);
    cudaFuncSetAttribute(k_mmagemm<1>, cudaFuncAttributeMaxDynamicSharedMemorySize, SM_TOTAL);
    cudaFuncSetAttribute(k_mmagemm<2>, cudaFuncAttributeMaxDynamicSharedMemorySize, SM_TOTAL);

    // --- CSR build ---
    k_zero_cnt<<<(MN + 255) / 256, 256>>>();
    k_count<<<(NE + 255) / 256, 256>>>(ei);
    k_scan<<<1, 1024>>>();
    k_fill<<<(NE + 255) / 256, 256>>>(ei);

    // --- weight conversion (tiled transpose + bf16 split) ---
    for (int i = 0; i < 6; i++) {
        dim3 g(WN[i] / 32, WK[i] / 32), blk(32, 8);
        k_wcvt<<<g, blk>>>(W[i], wH + (size_t)i * 65536, wL + (size_t)i * 65536, WK[i], WN[i]);
    }

    const int AGG_BLOCKS = (MN * 32 + 255) / 256;

    // --- layer 1 ---
    k_agg<1><<<AGG_BLOCKS, 256>>>(x, aggH, aggL);
    launch_gemm(2, aggH, aggL, wH + 0 * 65536, wL + 0 * 65536, Bv[0], nullptr, hH, hL, MN, 128, 128);
    launch_gemm(0, hH, hL,     wH + 1 * 65536, wL + 1 * 65536, Bv[1], f32, nullptr, nullptr, MN, 128, 256);

    // --- layer 2 ---
    k_agg<2><<<AGG_BLOCKS, 256>>>(f32, aggH, aggL);
    launch_gemm(2, aggH, aggL, wH + 2 * 65536, wL + 2 * 65536, Bv[2], nullptr, hH, hL, MN, 256, 256);
    launch_gemm(0, hH, hL,     wH + 3 * 65536, wL + 3 * 65536, Bv[3], f32, nullptr, nullptr, MN, 256, 128);

    // --- layer 3 ---
    k_agg<1><<<AGG_BLOCKS, 256>>>(f32, aggH, aggL);
    launch_gemm(2, aggH, aggL, wH + 4 * 65536, wL + 4 * 65536, Bv[4], nullptr, hH, hL, MN, 128, 128);
    launch_gemm(1, hH, hL,     wH + 5 * 65536, wL + 5 * 65536, Bv[5], out, nullptr, nullptr, MN, 128, 128);
}

// round 7
// speedup vs baseline: 1.9854x; 1.1995x over previous
#include <cuda_runtime.h>
#include <cuda_fp16.h>
#include <cstdint>

#define MN  50000
#define MNP 50176          // padded to 392*128 (unconditional GEMM tile loads)
#define NE  800000

// ---------------- scratch (device globals; no allocs allowed) ---------------
__device__ __half g_agg[(size_t)MNP * 256];     // aggregation out (fp16)
__device__ __half g_h[(size_t)MNP * 256];       // hidden (fp16)
__device__ float  g_f32[(size_t)MNP * 256];     // layer out (fp32, next agg input)
__device__ __half g_wHi[6][65536];              // weight hi (transposed [N,K])
__device__ __half g_wLo[6][65536];              // weight lo
__device__ int g_row[MN + 1];
__device__ int g_cnt[MN];
__device__ int g_srcs[NE];

// ---------------- helpers ---------------------------------------------------
__device__ __forceinline__ uint32_t smem_u32(const void* p) {
    return (uint32_t)__cvta_generic_to_shared((void*)p);
}
__device__ __forceinline__ void cp_async16(uint32_t dst, const void* src) {
    asm volatile("cp.async.cg.shared.global [%0], [%1], 16;" :: "r"(dst), "l"(src));
}
__device__ __forceinline__ void cp_commit() {
    asm volatile("cp.async.commit_group;" ::: "memory");
}
template <int n>
__device__ __forceinline__ void cp_wait() {
    asm volatile("cp.async.wait_group %0;" :: "n"(n) : "memory");
}
__device__ __forceinline__ void ldsm_x4(uint32_t& r0, uint32_t& r1, uint32_t& r2,
                                        uint32_t& r3, uint32_t addr) {
    asm volatile("ldmatrix.sync.aligned.m8n8.x4.shared.b16 {%0,%1,%2,%3}, [%4];"
                 : "=r"(r0), "=r"(r1), "=r"(r2), "=r"(r3) : "r"(addr));
}

// ---------------- CSR build -------------------------------------------------
__global__ void k_zero_cnt() {
    int i = blockIdx.x * blockDim.x + threadIdx.x;
    if (i < MN) g_cnt[i] = 0;
}
__global__ void k_count(const int* __restrict__ ei) {
    int e = blockIdx.x * blockDim.x + threadIdx.x;
    if (e < NE) {
        int dst = ei[NE + e];
        if (dst >= 0 && dst < MN) atomicAdd(&g_cnt[dst], 1);
    }
}
__global__ void k_scan() {
    __shared__ int ssum[1024];
    const int t = threadIdx.x;
    const int CH = (MN + 1023) / 1024;
    const int base = t * CH;
    int s = 0;
    for (int i = 0; i < CH; i++) { int idx = base + i; if (idx < MN) s += g_cnt[idx]; }
    ssum[t] = s;
    __syncthreads();
    for (int off = 1; off < 1024; off <<= 1) {
        int v = (t >= off) ? ssum[t - off] : 0;
        __syncthreads();
        ssum[t] += v;
        __syncthreads();
    }
    int run = ssum[t] - s;
    for (int i = 0; i < CH; i++) {
        int idx = base + i;
        if (idx < MN) { int c = g_cnt[idx]; g_row[idx] = run; run += c; g_cnt[idx] = 0; }
    }
    if (t == 1023) g_row[MN] = ssum[1023];
}
__global__ void k_fill(const int* __restrict__ ei) {
    int e = blockIdx.x * blockDim.x + threadIdx.x;
    if (e < NE) {
        int src = ei[e];
        int dst = ei[NE + e];
        if (src >= 0 && src < MN && dst >= 0 && dst < MN) {
            int pos = atomicAdd(&g_cnt[dst], 1);
            g_srcs[g_row[dst] + pos] = src;
        }
    }
}

// ---------------- weight convert: W[K,N] fp32 -> hi/lo fp16 [N,K] -----------
__global__ void k_wcvt(const float* __restrict__ W, __half* __restrict__ hi,
                       __half* __restrict__ lo, int K, int N) {
    __shared__ float t[32][33];
    const int kb = blockIdx.y * 32, nb = blockIdx.x * 32;
    const int tx = threadIdx.x, ty0 = threadIdx.y;
#pragma unroll
    for (int i = 0; i < 4; i++) {
        int ty = ty0 + 8 * i;
        t[ty][tx] = W[(size_t)(kb + ty) * N + nb + tx];
    }
    __syncthreads();
#pragma unroll
    for (int i = 0; i < 4; i++) {
        int n = ty0 + 8 * i;
        float v = t[tx][n];
        __half h = __float2half_rn(v);
        hi[(size_t)(nb + n) * K + kb + tx] = h;
        lo[(size_t)(nb + n) * K + kb + tx] = __float2half_rn(v - __half2float(h));
    }
}

// ---------------- aggregation: fp32 in -> fp16 out --------------------------
template <int VEC>
__global__ void k_agg(const float* __restrict__ x, __half* __restrict__ oh) {
    const int node = (blockIdx.x * blockDim.x + threadIdx.x) >> 5;
    if (node >= MN) return;
    const int lane = threadIdx.x & 31;
    const int F = VEC * 128;

    float4 acc[VEC];
    const float4* xr = (const float4*)(x + (size_t)node * F);
#pragma unroll
    for (int v = 0; v < VEC; v++) acc[v] = xr[lane + 32 * v];

    const int s = g_row[node];
    const int e = g_row[node + 1];
    for (int i = s; i < e; i += 32) {
        const int my = (i + lane < e) ? g_srcs[i + lane] : 0;
        const int cnt = min(32, e - i);
        for (int t = 0; t < cnt; t++) {
            const int src = __shfl_sync(0xffffffff, my, t);
            const float4* xs = (const float4*)(x + (size_t)src * F);
#pragma unroll
            for (int v = 0; v < VEC; v++) {
                float4 q = __ldg(&xs[lane + 32 * v]);
                acc[v].x += q.x; acc[v].y += q.y; acc[v].z += q.z; acc[v].w += q.w;
            }
        }
    }
#pragma unroll
    for (int v = 0; v < VEC; v++) {
        __half2 p0 = __floats2half2_rn(acc[v].x, acc[v].y);
        __half2 p1 = __floats2half2_rn(acc[v].z, acc[v].w);
        size_t off = (size_t)node * F + lane * 4 + 128 * v;
        *(uint2*)(oh + off) = make_uint2(*(uint32_t*)&p0, *(uint32_t*)&p1);
    }
}

// ---------------- mma.sync fp16 GEMM, 2-pass (A fp16, W hi+lo) ---------------
// C[M,N] = act(A[M,K] @ W[K,N] + bias) = act(A@(Whi+Wlo) + b)
// EPI: 0 = fp32+ReLU, 1 = fp32, 2 = fp16 + ReLU
#define PITCH 40                   // fp16 elems per smem row (80B, conflict-free)
#define TILE_B 10240               // one 128x32 fp16 array, 80B rows
#define BUF_B  (3 * TILE_B)        // A, Bh, Bl
#define SM_TOTAL (2 * BUF_B + 512)

__device__ __forceinline__ void mma16816(float* d, const uint32_t* a, const uint32_t* b) {
    asm volatile("mma.sync.aligned.m16n8k16.row.col.f32.f16.f16.f32 "
                 "{%0,%1,%2,%3}, {%4,%5,%6,%7}, {%8,%9}, {%0,%1,%2,%3};"
                 : "+f"(d[0]), "+f"(d[1]), "+f"(d[2]), "+f"(d[3])
                 : "r"(a[0]), "r"(a[1]), "r"(a[2]), "r"(a[3]), "r"(b[0]), "r"(b[1]));
}

__device__ __forceinline__ void load_tile(
    char* smbase, const __half* __restrict__ A, const __half* __restrict__ Bhi,
    const __half* __restrict__ Blo, int tid, int m0, int n0, int K, int kb) {
    const uint32_t s0 = smem_u32(smbase);
#pragma unroll
    for (int i = 0; i < 2; i++) {
        const int idx = tid + 256 * i;
        const int r = idx >> 2, c4 = idx & 3;
        const uint32_t so = (uint32_t)(r * 80 + c4 * 16);
        const size_t aoff = (size_t)(m0 + r) * K + kb + c4 * 8;
        const size_t boff = (size_t)(n0 + r) * K + kb + c4 * 8;
        cp_async16(s0 + so,              A   + aoff);
        cp_async16(s0 + TILE_B + so,     Bhi + boff);
        cp_async16(s0 + 2 * TILE_B + so, Blo + boff);
    }
}

template <int EPI>
__global__ __launch_bounds__(256, 2)
void k_mmagemm(const __half* __restrict__ A, const __half* __restrict__ Bhi,
               const __half* __restrict__ Blo, const float* __restrict__ bias,
               float* __restrict__ outF, __half* __restrict__ outH,
               int M, int K, int N) {
    extern __shared__ char sm[];
    float* sbias = (float*)(sm + 2 * BUF_B);

    const int tid = threadIdx.x, warp = tid >> 5, lane = tid & 31;
    const int g = lane >> 2, tig = lane & 3;
    const int wm = warp >> 1, wn = warp & 1;      // 4x2 warp grid, 32x64 warp tile
    const int m0 = blockIdx.x * 128, n0 = blockIdx.y * 128;

    if (tid < 128) sbias[tid] = bias[n0 + tid];

    // ldmatrix per-lane offsets (bytes from array base)
    const int aRow = wm * 32 + (lane & 15);
    const int aCol = (lane & 16) ? 8 : 0;
    const uint32_t aOffB = (uint32_t)(aRow * PITCH + aCol) * 2;
    const int bRow = wn * 64 + (lane & 7) + ((lane & 16) ? 8 : 0);
    const int bCol = (lane & 8) ? 8 : 0;
    const uint32_t bOffB = (uint32_t)(bRow * PITCH + bCol) * 2;

    float acc[2][8][4];
#pragma unroll
    for (int i = 0; i < 2; i++)
#pragma unroll
        for (int j = 0; j < 8; j++)
#pragma unroll
            for (int r = 0; r < 4; r++) acc[i][j][r] = 0.f;

    const int NKT = K >> 5;
    load_tile(sm, A, Bhi, Blo, tid, m0, n0, K, 0);
    cp_commit();
    const uint32_t smu = smem_u32(sm);

    for (int kt = 0; kt < NKT; kt++) {
        const int b = kt & 1;
        if (kt + 1 < NKT) {
            __syncthreads();
            load_tile(sm + (b ^ 1) * BUF_B, A, Bhi, Blo, tid, m0, n0, K, (kt + 1) * 32);
            cp_commit();
            cp_wait<1>();
        } else {
            cp_wait<0>();
        }
        __syncthreads();

        const uint32_t sAU  = smu + b * BUF_B;
        const uint32_t sBhU = sAU + TILE_B;
        const uint32_t sBlU = sAU + 2 * TILE_B;

#pragma unroll
        for (int k16 = 0; k16 < 2; k16++) {
            const uint32_t kByte = (uint32_t)(k16 * 16 * 2);
            uint32_t a[2][4];
#pragma unroll
            for (int i = 0; i < 2; i++)
                ldsm_x4(a[i][0], a[i][1], a[i][2], a[i][3],
                        sAU + aOffB + kByte + (uint32_t)(i * 16 * PITCH * 2));
#pragma unroll
            for (int pass = 0; pass < 2; pass++) {
                const uint32_t bBase = ((pass == 0) ? sBhU : sBlU) + bOffB + kByte;
                uint32_t b2[8][2];
#pragma unroll
                for (int jj = 0; jj < 4; jj++)
                    ldsm_x4(b2[2 * jj][0], b2[2 * jj][1], b2[2 * jj + 1][0], b2[2 * jj + 1][1],
                            bBase + (uint32_t)(jj * 16 * PITCH * 2));
#pragma unroll
                for (int i = 0; i < 2; i++)
#pragma unroll
                    for (int j = 0; j < 8; j++) mma16816(acc[i][j], a[i], b2[j]);
            }
        }
    }

    // epilogue (registers + sbias only)
#pragma unroll
    for (int i = 0; i < 2; i++) {
        const int r0 = m0 + wm * 32 + i * 16 + g;
#pragma unroll
        for (int half = 0; half < 2; half++) {
            const int row = r0 + half * 8;
            if (row >= M) continue;
#pragma unroll
            for (int j = 0; j < 8; j++) {
                const int cl = wn * 64 + j * 8 + tig * 2;
                float v0 = acc[i][j][2 * half + 0] + sbias[cl];
                float v1 = acc[i][j][2 * half + 1] + sbias[cl + 1];
                if (EPI != 1) { v0 = fmaxf(v0, 0.f); v1 = fmaxf(v1, 0.f); }
                const size_t o = (size_t)row * N + n0 + cl;
                if (EPI == 2) {
                    __half2 hp = __floats2half2_rn(v0, v1);
                    *(uint32_t*)(outH + o) = *(uint32_t*)&hp;
                } else {
                    *(float2*)(outF + o) = make_float2(v0, v1);
                }
            }
        }
    }
}

// ---------------- launch ----------------------------------------------------
static inline void launch_gemm(int epi, const __half* A, const __half* Bhi, const __half* Blo,
                               const float* bias, float* outF, __half* outH,
                               int M, int K, int N) {
    dim3 grid((M + 127) / 128, N / 128);
    if (epi == 0)      k_mmagemm<0><<<grid, 256, SM_TOTAL>>>(A, Bhi, Blo, bias, outF, outH, M, K, N);
    else if (epi == 1) k_mmagemm<1><<<grid, 256, SM_TOTAL>>>(A, Bhi, Blo, bias, outF, outH, M, K, N);
    else               k_mmagemm<2><<<grid, 256, SM_TOTAL>>>(A, Bhi, Blo, bias, outF, outH, M, K, N);
}

extern "C" void kernel_launch(void* const* d_in, const int* in_sizes, int n_in,
                              void* d_out, int out_size) {
    const float* x  = (const float*)d_in[0];
    const int*   ei = (const int*)d_in[1];   // int32 (JAX x64 disabled)
    const float* W[6]  = {(const float*)d_in[2], (const float*)d_in[4], (const float*)d_in[6],
                          (const float*)d_in[8], (const float*)d_in[10], (const float*)d_in[12]};
    const float* Bv[6] = {(const float*)d_in[3], (const float*)d_in[5], (const float*)d_in[7],
                          (const float*)d_in[9], (const float*)d_in[11], (const float*)d_in[13]};
    const int WK[6] = {128, 128, 256, 256, 128, 128};
    const int WN[6] = {128, 256, 256, 128, 128, 128};
    float* out = (float*)d_out;

    __half *agg, *h, *wHi, *wLo;
    float* f32;
    cudaGetSymbolAddress((void**)&agg, g_agg);
    cudaGetSymbolAddress((void**)&h, g_h);
    cudaGetSymbolAddress((void**)&wHi, g_wHi);
    cudaGetSymbolAddress((void**)&wLo, g_wLo);
    cudaGetSymbolAddress((void**)&f32, g_f32);

    cudaFuncSetAttribute(k_mmagemm<0>, cudaFuncAttributeMaxDynamicSharedMemorySize, SM_TOTAL);
    cudaFuncSetAttribute(k_mmagemm<1>, cudaFuncAttributeMaxDynamicSharedMemorySize, SM_TOTAL);
    cudaFuncSetAttribute(k_mmagemm<2>, cudaFuncAttributeMaxDynamicSharedMemorySize, SM_TOTAL);

    // --- CSR build ---
    k_zero_cnt<<<(MN + 255) / 256, 256>>>();
    k_count<<<(NE + 255) / 256, 256>>>(ei);
    k_scan<<<1, 1024>>>();
    k_fill<<<(NE + 255) / 256, 256>>>(ei);

    // --- weight conversion (tiled transpose + fp16 hi/lo split) ---
    for (int i = 0; i < 6; i++) {
        dim3 g(WN[i] / 32, WK[i] / 32), blk(32, 8);
        k_wcvt<<<g, blk>>>(W[i], wHi + (size_t)i * 65536, wLo + (size_t)i * 65536, WK[i], WN[i]);
    }

    const int AGG_BLOCKS = (MN * 32 + 255) / 256;

    // --- layer 1 ---
    k_agg<1><<<AGG_BLOCKS, 256>>>(x, agg);
    launch_gemm(2, agg, wHi + 0 * 65536, wLo + 0 * 65536, Bv[0], nullptr, h, MN, 128, 128);
    launch_gemm(0, h,   wHi + 1 * 65536, wLo + 1 * 65536, Bv[1], f32, nullptr, MN, 128, 256);

    // --- layer 2 ---
    k_agg<2><<<AGG_BLOCKS, 256>>>(f32, agg);
    launch_gemm(2, agg, wHi + 2 * 65536, wLo + 2 * 65536, Bv[2], nullptr, h, MN, 256, 256);
    launch_gemm(0, h,   wHi + 3 * 65536, wLo + 3 * 65536, Bv[3], f32, nullptr, MN, 256, 128);

    // --- layer 3 ---
    k_agg<1><<<AGG_BLOCKS, 256>>>(f32, agg);
    launch_gemm(2, agg, wHi + 4 * 65536, wLo + 4 * 65536, Bv[4], nullptr, h, MN, 128, 128);
    launch_gemm(1, h,   wHi + 5 * 65536, wLo + 5 * 65536, Bv[5], out, nullptr, MN, 128, 128);
}

// round 9
// speedup vs baseline: 2.1048x; 1.0601x over previous
#include <cuda_runtime.h>
#include <cuda_fp16.h>
#include <cstdint>

#define MN  50000
#define MNP 50176          // padded to 392*128 (unconditional GEMM tile loads)
#define NE  800000

// ---------------- scratch (device globals; no allocs allowed) ---------------
__device__ __half g_agg[(size_t)MNP * 256];     // aggregation out (GEMM A input)
__device__ __half g_h[(size_t)MNP * 256];       // MLP hidden
__device__ __half g_act[(size_t)MNP * 256];     // layer output (next agg input)
__device__ __half g_wHi[6][65536];              // weight hi (transposed [N,K])
__device__ __half g_wLo[6][65536];              // weight lo
__device__ int g_row[MN + 1];
__device__ int g_cnt[MN];
__device__ int g_srcs[NE];

// ---------------- helpers ---------------------------------------------------
__device__ __forceinline__ uint32_t smem_u32(const void* p) {
    return (uint32_t)__cvta_generic_to_shared((void*)p);
}
__device__ __forceinline__ void cp_async16(uint32_t dst, const void* src) {
    asm volatile("cp.async.cg.shared.global [%0], [%1], 16;" :: "r"(dst), "l"(src));
}
__device__ __forceinline__ void cp_commit() {
    asm volatile("cp.async.commit_group;" ::: "memory");
}
template <int n>
__device__ __forceinline__ void cp_wait() {
    asm volatile("cp.async.wait_group %0;" :: "n"(n) : "memory");
}
__device__ __forceinline__ void ldsm_x4(uint32_t& r0, uint32_t& r1, uint32_t& r2,
                                        uint32_t& r3, uint32_t addr) {
    asm volatile("ldmatrix.sync.aligned.m8n8.x4.shared.b16 {%0,%1,%2,%3}, [%4];"
                 : "=r"(r0), "=r"(r1), "=r"(r2), "=r"(r3) : "r"(addr));
}

// ---------------- CSR build -------------------------------------------------
__global__ void k_zero_cnt() {
    int i = blockIdx.x * blockDim.x + threadIdx.x;
    if (i < MN) g_cnt[i] = 0;
}
__global__ void k_count(const int* __restrict__ ei) {
    int e = blockIdx.x * blockDim.x + threadIdx.x;
    if (e < NE) {
        int dst = ei[NE + e];
        if (dst >= 0 && dst < MN) atomicAdd(&g_cnt[dst], 1);
    }
}
__global__ void k_scan() {
    __shared__ int ssum[1024];
    const int t = threadIdx.x;
    const int CH = (MN + 1023) / 1024;
    const int base = t * CH;
    int s = 0;
    for (int i = 0; i < CH; i++) { int idx = base + i; if (idx < MN) s += g_cnt[idx]; }
    ssum[t] = s;
    __syncthreads();
    for (int off = 1; off < 1024; off <<= 1) {
        int v = (t >= off) ? ssum[t - off] : 0;
        __syncthreads();
        ssum[t] += v;
        __syncthreads();
    }
    int run = ssum[t] - s;
    for (int i = 0; i < CH; i++) {
        int idx = base + i;
        if (idx < MN) { int c = g_cnt[idx]; g_row[idx] = run; run += c; g_cnt[idx] = 0; }
    }
    if (t == 1023) g_row[MN] = ssum[1023];
}
__global__ void k_fill(const int* __restrict__ ei) {
    int e = blockIdx.x * blockDim.x + threadIdx.x;
    if (e < NE) {
        int src = ei[e];
        int dst = ei[NE + e];
        if (src >= 0 && src < MN && dst >= 0 && dst < MN) {
            int pos = atomicAdd(&g_cnt[dst], 1);
            g_srcs[g_row[dst] + pos] = src;
        }
    }
}

// ---------------- weight convert: W[K,N] fp32 -> hi/lo fp16 [N,K] -----------
__global__ void k_wcvt(const float* __restrict__ W, __half* __restrict__ hi,
                       __half* __restrict__ lo, int K, int N) {
    __shared__ float t[32][33];
    const int kb = blockIdx.y * 32, nb = blockIdx.x * 32;
    const int tx = threadIdx.x, ty0 = threadIdx.y;
#pragma unroll
    for (int i = 0; i < 4; i++) {
        int ty = ty0 + 8 * i;
        t[ty][tx] = W[(size_t)(kb + ty) * N + nb + tx];
    }
    __syncthreads();
#pragma unroll
    for (int i = 0; i < 4; i++) {
        int n = ty0 + 8 * i;
        float v = t[tx][n];
        __half h = __float2half_rn(v);
        hi[(size_t)(nb + n) * K + kb + tx] = h;
        lo[(size_t)(nb + n) * K + kb + tx] = __float2half_rn(v - __half2float(h));
    }
}

// ---------------- aggregation: (fp32|fp16 in) -> fp16 out, fp32 accum -------
__device__ __forceinline__ float4 load4(const float* p) {
    return *(const float4*)p;
}
__device__ __forceinline__ float4 load4(const __half* p) {
    uint2 u = __ldg((const uint2*)p);
    float2 a = __half22float2(*(__half2*)&u.x);
    float2 b = __half22float2(*(__half2*)&u.y);
    return make_float4(a.x, a.y, b.x, b.y);
}

template <int VEC, typename T>
__global__ void k_agg(const T* __restrict__ x, __half* __restrict__ oh) {
    const int node = (blockIdx.x * blockDim.x + threadIdx.x) >> 5;
    if (node >= MN) return;
    const int lane = threadIdx.x & 31;
    const int F = VEC * 128;

    float4 acc[VEC];
#pragma unroll
    for (int v = 0; v < VEC; v++)
        acc[v] = load4(x + (size_t)node * F + (lane + 32 * v) * 4);

    const int s = g_row[node];
    const int e = g_row[node + 1];
    for (int i = s; i < e; i += 32) {
        const int my = (i + lane < e) ? g_srcs[i + lane] : 0;
        const int cnt = min(32, e - i);
        for (int t = 0; t < cnt; t++) {
            const int src = __shfl_sync(0xffffffff, my, t);
            const T* xs = x + (size_t)src * F;
#pragma unroll
            for (int v = 0; v < VEC; v++) {
                float4 q = load4(xs + (lane + 32 * v) * 4);
                acc[v].x += q.x; acc[v].y += q.y; acc[v].z += q.z; acc[v].w += q.w;
            }
        }
    }
#pragma unroll
    for (int v = 0; v < VEC; v++) {
        __half2 p0 = __floats2half2_rn(acc[v].x, acc[v].y);
        __half2 p1 = __floats2half2_rn(acc[v].z, acc[v].w);
        size_t off = (size_t)node * F + (lane + 32 * v) * 4;
        *(uint2*)(oh + off) = make_uint2(*(uint32_t*)&p0, *(uint32_t*)&p1);
    }
}

// ---------------- mma.sync fp16 GEMM, 2-pass (A fp16, W hi+lo) ---------------
// C[M,N] = act(A[M,K] @ (Whi+Wlo) + bias)
// EPI: 0 = fp16 + ReLU, 1 = fp32 (no ReLU, final output)
#define PITCH 40                   // fp16 elems per smem row (80B, conflict-free)
#define TILE_B 10240               // one 128x32 fp16 array, 80B rows
#define BUF_B  (3 * TILE_B)        // A, Bh, Bl
#define SM_TOTAL (2 * BUF_B + 512)

__device__ __forceinline__ void mma16816(float* d, const uint32_t* a, const uint32_t* b) {
    asm volatile("mma.sync.aligned.m16n8k16.row.col.f32.f16.f16.f32 "
                 "{%0,%1,%2,%3}, {%4,%5,%6,%7}, {%8,%9}, {%0,%1,%2,%3};"
                 : "+f"(d[0]), "+f"(d[1]), "+f"(d[2]), "+f"(d[3])
                 : "r"(a[0]), "r"(a[1]), "r"(a[2]), "r"(a[3]), "r"(b[0]), "r"(b[1]));
}

__device__ __forceinline__ void load_tile(
    char* smbase, const __half* __restrict__ A, const __half* __restrict__ Bhi,
    const __half* __restrict__ Blo, int tid, int m0, int n0, int K, int kb) {
    const uint32_t s0 = smem_u32(smbase);
#pragma unroll
    for (int i = 0; i < 2; i++) {
        const int idx = tid + 256 * i;
        const int r = idx >> 2, c4 = idx & 3;
        const uint32_t so = (uint32_t)(r * 80 + c4 * 16);
        const size_t aoff = (size_t)(m0 + r) * K + kb + c4 * 8;
        const size_t boff = (size_t)(n0 + r) * K + kb + c4 * 8;
        cp_async16(s0 + so,              A   + aoff);
        cp_async16(s0 + TILE_B + so,     Bhi + boff);
        cp_async16(s0 + 2 * TILE_B + so, Blo + boff);
    }
}

template <int EPI>
__global__ __launch_bounds__(256, 2)
void k_mmagemm(const __half* __restrict__ A, const __half* __restrict__ Bhi,
               const __half* __restrict__ Blo, const float* __restrict__ bias,
               float* __restrict__ outF, __half* __restrict__ outH,
               int M, int K, int N) {
    extern __shared__ char sm[];
    float* sbias = (float*)(sm + 2 * BUF_B);

    const int tid = threadIdx.x, warp = tid >> 5, lane = tid & 31;
    const int g = lane >> 2, tig = lane & 3;
    const int wm = warp >> 1, wn = warp & 1;      // 4x2 warp grid, 32x64 warp tile
    const int m0 = blockIdx.x * 128, n0 = blockIdx.y * 128;

    if (tid < 128) sbias[tid] = bias[n0 + tid];

    const int aRow = wm * 32 + (lane & 15);
    const int aCol = (lane & 16) ? 8 : 0;
    const uint32_t aOffB = (uint32_t)(aRow * PITCH + aCol) * 2;
    const int bRow = wn * 64 + (lane & 7) + ((lane & 16) ? 8 : 0);
    const int bCol = (lane & 8) ? 8 : 0;
    const uint32_t bOffB = (uint32_t)(bRow * PITCH + bCol) * 2;

    float acc[2][8][4];
#pragma unroll
    for (int i = 0; i < 2; i++)
#pragma unroll
        for (int j = 0; j < 8; j++)
#pragma unroll
            for (int r = 0; r < 4; r++) acc[i][j][r] = 0.f;

    const int NKT = K >> 5;
    load_tile(sm, A, Bhi, Blo, tid, m0, n0, K, 0);
    cp_commit();
    const uint32_t smu = smem_u32(sm);

    for (int kt = 0; kt < NKT; kt++) {
        const int b = kt & 1;
        if (kt + 1 < NKT) {
            __syncthreads();
            load_tile(sm + (b ^ 1) * BUF_B, A, Bhi, Blo, tid, m0, n0, K, (kt + 1) * 32);
            cp_commit();
            cp_wait<1>();
        } else {
            cp_wait<0>();
        }
        __syncthreads();

        const uint32_t sAU  = smu + b * BUF_B;
        const uint32_t sBhU = sAU + TILE_B;
        const uint32_t sBlU = sAU + 2 * TILE_B;

#pragma unroll
        for (int k16 = 0; k16 < 2; k16++) {
            const uint32_t kByte = (uint32_t)(k16 * 16 * 2);
            uint32_t a[2][4];
#pragma unroll
            for (int i = 0; i < 2; i++)
                ldsm_x4(a[i][0], a[i][1], a[i][2], a[i][3],
                        sAU + aOffB + kByte + (uint32_t)(i * 16 * PITCH * 2));
#pragma unroll
            for (int pass = 0; pass < 2; pass++) {
                const uint32_t bBase = ((pass == 0) ? sBhU : sBlU) + bOffB + kByte;
                uint32_t b2[8][2];
#pragma unroll
                for (int jj = 0; jj < 4; jj++)
                    ldsm_x4(b2[2 * jj][0], b2[2 * jj][1], b2[2 * jj + 1][0], b2[2 * jj + 1][1],
                            bBase + (uint32_t)(jj * 16 * PITCH * 2));
#pragma unroll
                for (int i = 0; i < 2; i++)
#pragma unroll
                    for (int j = 0; j < 8; j++) mma16816(acc[i][j], a[i], b2[j]);
            }
        }
    }

    // epilogue
#pragma unroll
    for (int i = 0; i < 2; i++) {
        const int r0 = m0 + wm * 32 + i * 16 + g;
#pragma unroll
        for (int half = 0; half < 2; half++) {
            const int row = r0 + half * 8;
            if (row >= M) continue;
#pragma unroll
            for (int j = 0; j < 8; j++) {
                const int cl = wn * 64 + j * 8 + tig * 2;
                float v0 = acc[i][j][2 * half + 0] + sbias[cl];
                float v1 = acc[i][j][2 * half + 1] + sbias[cl + 1];
                const size_t o = (size_t)row * N + n0 + cl;
                if (EPI == 0) {
                    v0 = fmaxf(v0, 0.f);
                    v1 = fmaxf(v1, 0.f);
                    __half2 hp = __floats2half2_rn(v0, v1);
                    *(uint32_t*)(outH + o) = *(uint32_t*)&hp;
                } else {
                    *(float2*)(outF + o) = make_float2(v0, v1);
                }
            }
        }
    }
}

// ---------------- launch ----------------------------------------------------
static inline void launch_gemm(int epi, const __half* A, const __half* Bhi, const __half* Blo,
                               const float* bias, float* outF, __half* outH,
                               int M, int K, int N) {
    dim3 grid((M + 127) / 128, N / 128);
    if (epi == 0) k_mmagemm<0><<<grid, 256, SM_TOTAL>>>(A, Bhi, Blo, bias, outF, outH, M, K, N);
    else          k_mmagemm<1><<<grid, 256, SM_TOTAL>>>(A, Bhi, Blo, bias, outF, outH, M, K, N);
}

extern "C" void kernel_launch(void* const* d_in, const int* in_sizes, int n_in,
                              void* d_out, int out_size) {
    const float* x  = (const float*)d_in[0];
    const int*   ei = (const int*)d_in[1];   // int32 (JAX x64 disabled)
    const float* W[6]  = {(const float*)d_in[2], (const float*)d_in[4], (const float*)d_in[6],
                          (const float*)d_in[8], (const float*)d_in[10], (const float*)d_in[12]};
    const float* Bv[6] = {(const float*)d_in[3], (const float*)d_in[5], (const float*)d_in[7],
                          (const float*)d_in[9], (const float*)d_in[11], (const float*)d_in[13]};
    const int WK[6] = {128, 128, 256, 256, 128, 128};
    const int WN[6] = {128, 256, 256, 128, 128, 128};
    float* out = (float*)d_out;

    __half *agg, *h, *act, *wHi, *wLo;
    cudaGetSymbolAddress((void**)&agg, g_agg);
    cudaGetSymbolAddress((void**)&h, g_h);
    cudaGetSymbolAddress((void**)&act, g_act);
    cudaGetSymbolAddress((void**)&wHi, g_wHi);
    cudaGetSymbolAddress((void**)&wLo, g_wLo);

    cudaFuncSetAttribute(k_mmagemm<0>, cudaFuncAttributeMaxDynamicSharedMemorySize, SM_TOTAL);
    cudaFuncSetAttribute(k_mmagemm<1>, cudaFuncAttributeMaxDynamicSharedMemorySize, SM_TOTAL);

    // --- CSR build ---
    k_zero_cnt<<<(MN + 255) / 256, 256>>>();
    k_count<<<(NE + 255) / 256, 256>>>(ei);
    k_scan<<<1, 1024>>>();
    k_fill<<<(NE + 255) / 256, 256>>>(ei);

    // --- weight conversion (tiled transpose + fp16 hi/lo split) ---
    for (int i = 0; i < 6; i++) {
        dim3 g(WN[i] / 32, WK[i] / 32), blk(32, 8);
        k_wcvt<<<g, blk>>>(W[i], wHi + (size_t)i * 65536, wLo + (size_t)i * 65536, WK[i], WN[i]);
    }

    const int AGG_BLOCKS = (MN * 32 + 255) / 256;

    // --- layer 1 (agg reads fp32 harness input) ---
    k_agg<1, float><<<AGG_BLOCKS, 256>>>(x, agg);
    launch_gemm(0, agg, wHi + 0 * 65536, wLo + 0 * 65536, Bv[0], nullptr, h, MN, 128, 128);
    launch_gemm(0, h,   wHi + 1 * 65536, wLo + 1 * 65536, Bv[1], nullptr, act, MN, 128, 256);

    // --- layer 2 (fp16 gather) ---
    k_agg<2, __half><<<AGG_BLOCKS, 256>>>(act, agg);
    launch_gemm(0, agg, wHi + 2 * 65536, wLo + 2 * 65536, Bv[2], nullptr, h, MN, 256, 256);
    launch_gemm(0, h,   wHi + 3 * 65536, wLo + 3 * 65536, Bv[3], nullptr, act, MN, 256, 128);

    // --- layer 3 (fp16 gather) ---
    k_agg<1, __half><<<AGG_BLOCKS, 256>>>(act, agg);
    launch_gemm(0, agg, wHi + 4 * 65536, wLo + 4 * 65536, Bv[4], nullptr, h, MN, 128, 128);
    launch_gemm(1, h,   wHi + 5 * 65536, wLo + 5 * 65536, Bv[5], out, nullptr, MN, 128, 128);
}